// round 4
// baseline (speedup 1.0000x reference)
#include <cuda_runtime.h>
#include <cuda_bf16.h>
#include <math.h>

#define DD 512
#define SS 256
#define BB 32
#define TT 24
#define NROWS (BB*SS)   // 8192

// ---------------- device scratch (static: no runtime allocation) ----------------
__device__ float g_bcat[512];                      // fc1_b + fc2_b
__device__ float g_co[NROWS*512];
__device__ __nv_bfloat16 g_codm[NROWS*512];        // bf16: only feeds tanh()
__device__ float g_qm[TT*BB*512];                  // qm projection of all question steps
__device__ float g_r[BB*512];
__device__ float g_add[BB*512];
__device__ float g_trr[BB*512];
__device__ float g_logits[BB*SS];

// ---------------- helpers ----------------
__device__ __forceinline__ float tanh_fast(float x){
    float ax = fabsf(x);
    float e  = __expf(fminf(ax, 15.0f) * 2.0f);
    float t  = __fdividef(e - 1.0f, e + 1.0f);
    return copysignf(t, x);
}

__device__ __forceinline__ float tanh_mufu(float x){
    float y;
    asm("tanh.approx.f32 %0, %1;" : "=f"(y) : "f"(x));
    return y;
}

__device__ __forceinline__ float warp_sum(float v){
#pragma unroll
    for (int o = 16; o; o >>= 1) v += __shfl_xor_sync(0xffffffffu, v, o);
    return v;
}

// ---------------- tiny prep: bias concat + r zero ----------------
__global__ __launch_bounds__(256) void prep_small(const float* __restrict__ fc1b,
                                                  const float* __restrict__ fc2b){
    int v = blockIdx.x * 256 + threadIdx.x;     // 64 blocks = 16384 threads
    if (v < 512)    g_bcat[v] = fc1b[v] + fc2b[v];
    if (v < BB*512) g_r[v]    = 0.0f;
}

// ---------------- fused GEMM launch A ----------------
// blocks [0,256):  co = perm(ctx)@fc1^T + perm(img)@fc2^T + bcat   (128x128 tile, K=2x512)
// blocks [256,352): qm = qout@qm_w^T + qm_b                        (64x64 tile, K=512)
__global__ __launch_bounds__(256) void gemm_A(const float* __restrict__ ctx,
                                              const float* __restrict__ img,
                                              const float* __restrict__ fc1w,
                                              const float* __restrict__ fc2w,
                                              const float* __restrict__ qout,
                                              const float* __restrict__ qmw,
                                              const float* __restrict__ qmb)
{
    __shared__ __align__(16) float sh[16*132*2];
    const int bid = blockIdx.x;
    const int tid = threadIdx.x;

    if (bid < 256){
        float* As = sh;
        float* Bs = sh + 16*132;
        const int m0  = (bid >> 2) * 128;
        const int n0  = (bid & 3) * 128;
        const int tx  = tid & 15, ty = tid >> 4;
        const int lr0 = tid >> 2;
        const int lc4 = (tid & 3) * 4;

        const int r1 = m0 + lr0, r2 = r1 + 64;
        const int p1 = (r1 & 255)*32 + (r1 >> 8);
        const int p2 = (r2 & 255)*32 + (r2 >> 8);

        float acc[8][8] = {};

#pragma unroll 1
        for (int half = 0; half < 2; half++){
            const float* Asrc = half ? img  : ctx;
            const float* Wsrc = half ? fc2w : fc1w;
            const float* A1 = Asrc + (size_t)p1*512 + lc4;
            const float* A2 = Asrc + (size_t)p2*512 + lc4;
            const float* W1 = Wsrc + (size_t)(n0 + lr0)*512 + lc4;
            const float* W2 = Wsrc + (size_t)(n0 + lr0 + 64)*512 + lc4;
            for (int kt = 0; kt < 512; kt += 16){
                float4 a0 = *(const float4*)(A1 + kt);
                float4 a1 = *(const float4*)(A2 + kt);
                float4 w0 = *(const float4*)(W1 + kt);
                float4 w1 = *(const float4*)(W2 + kt);
                __syncthreads();
                As[(lc4+0)*132 + lr0]      = a0.x; As[(lc4+1)*132 + lr0]      = a0.y;
                As[(lc4+2)*132 + lr0]      = a0.z; As[(lc4+3)*132 + lr0]      = a0.w;
                As[(lc4+0)*132 + lr0 + 64] = a1.x; As[(lc4+1)*132 + lr0 + 64] = a1.y;
                As[(lc4+2)*132 + lr0 + 64] = a1.z; As[(lc4+3)*132 + lr0 + 64] = a1.w;
                Bs[(lc4+0)*132 + lr0]      = w0.x; Bs[(lc4+1)*132 + lr0]      = w0.y;
                Bs[(lc4+2)*132 + lr0]      = w0.z; Bs[(lc4+3)*132 + lr0]      = w0.w;
                Bs[(lc4+0)*132 + lr0 + 64] = w1.x; Bs[(lc4+1)*132 + lr0 + 64] = w1.y;
                Bs[(lc4+2)*132 + lr0 + 64] = w1.z; Bs[(lc4+3)*132 + lr0 + 64] = w1.w;
                __syncthreads();
#pragma unroll
                for (int k = 0; k < 16; k++){
                    float4 af0 = *(const float4*)&As[k*132 + ty*8];
                    float4 af1 = *(const float4*)&As[k*132 + ty*8 + 4];
                    float4 bf0 = *(const float4*)&Bs[k*132 + tx*8];
                    float4 bf1 = *(const float4*)&Bs[k*132 + tx*8 + 4];
                    float av[8] = {af0.x,af0.y,af0.z,af0.w,af1.x,af1.y,af1.z,af1.w};
                    float bv[8] = {bf0.x,bf0.y,bf0.z,bf0.w,bf1.x,bf1.y,bf1.z,bf1.w};
#pragma unroll
                    for (int i = 0; i < 8; i++)
#pragma unroll
                        for (int j = 0; j < 8; j++)
                            acc[i][j] = fmaf(av[i], bv[j], acc[i][j]);
                }
            }
        }

        float4 bb0 = *(const float4*)&g_bcat[n0 + tx*8];
        float4 bb1 = *(const float4*)&g_bcat[n0 + tx*8 + 4];
        float bj[8] = {bb0.x,bb0.y,bb0.z,bb0.w,bb1.x,bb1.y,bb1.z,bb1.w};
#pragma unroll
        for (int i = 0; i < 8; i++){
            int m = m0 + ty*8 + i;
            float4 o0 = make_float4(acc[i][0]+bj[0], acc[i][1]+bj[1],
                                    acc[i][2]+bj[2], acc[i][3]+bj[3]);
            float4 o1 = make_float4(acc[i][4]+bj[4], acc[i][5]+bj[5],
                                    acc[i][6]+bj[6], acc[i][7]+bj[7]);
            *(float4*)&g_co[(size_t)m*512 + n0 + tx*8]     = o0;
            *(float4*)&g_co[(size_t)m*512 + n0 + tx*8 + 4] = o1;
        }
    } else {
        // ---- qm: 64x64 tile ----
        float* As = sh;            // stride 68
        float* Bs = sh + 16*68;
        const int qid = bid - 256;            // 0..95
        const int m0  = (qid >> 3) * 64;      // 12 tiles over M=768
        const int n0  = (qid & 7) * 64;       // 8 tiles over N=512
        const int tx  = tid & 15, ty = tid >> 4;
        const int lr0 = tid >> 2;             // 0..63
        const int lc4 = (tid & 3) * 4;

        float acc[4][4] = {};
        const float* A1 = qout + (size_t)(m0 + lr0)*512 + lc4;
        const float* W1 = qmw  + (size_t)(n0 + lr0)*512 + lc4;

        for (int kt = 0; kt < 512; kt += 16){
            float4 a0 = *(const float4*)(A1 + kt);
            float4 w0 = *(const float4*)(W1 + kt);
            __syncthreads();
            As[(lc4+0)*68 + lr0] = a0.x; As[(lc4+1)*68 + lr0] = a0.y;
            As[(lc4+2)*68 + lr0] = a0.z; As[(lc4+3)*68 + lr0] = a0.w;
            Bs[(lc4+0)*68 + lr0] = w0.x; Bs[(lc4+1)*68 + lr0] = w0.y;
            Bs[(lc4+2)*68 + lr0] = w0.z; Bs[(lc4+3)*68 + lr0] = w0.w;
            __syncthreads();
#pragma unroll
            for (int k = 0; k < 16; k++){
                float4 av = *(const float4*)&As[k*68 + ty*4];
                float4 bv = *(const float4*)&Bs[k*68 + tx*4];
                float aa[4] = {av.x,av.y,av.z,av.w};
                float bb[4] = {bv.x,bv.y,bv.z,bv.w};
#pragma unroll
                for (int i = 0; i < 4; i++)
#pragma unroll
                    for (int j = 0; j < 4; j++)
                        acc[i][j] = fmaf(aa[i], bb[j], acc[i][j]);
            }
        }

        float4 bq = *(const float4*)&qmb[n0 + tx*4];
        float bj[4] = {bq.x,bq.y,bq.z,bq.w};
#pragma unroll
        for (int i = 0; i < 4; i++){
            int m = m0 + ty*4 + i;
            float4 o = make_float4(acc[i][0]+bj[0], acc[i][1]+bj[1],
                                   acc[i][2]+bj[2], acc[i][3]+bj[3]);
            *(float4*)&g_qm[(size_t)m*512 + n0 + tx*4] = o;
        }
    }
}

// ---------------- codm GEMM: codm(bf16) = co @ dm_w^T + dm_b ----------------
__global__ __launch_bounds__(256) void sgemm_codm(const float* __restrict__ W,
                                                  const float* __restrict__ bias)
{
    __shared__ __align__(16) float As[16*132];
    __shared__ __align__(16) float Bs[16*132];
    const int m0  = blockIdx.y * 128;
    const int n0  = blockIdx.x * 128;
    const int tid = threadIdx.x;
    const int tx  = tid & 15, ty = tid >> 4;
    const int lr0 = tid >> 2;
    const int lc4 = (tid & 3) * 4;

    float acc[8][8] = {};
    const float* Abase = g_co + (size_t)(m0 + lr0) * 512 + lc4;
    const float* Wbase = W    + (size_t)(n0 + lr0) * 512 + lc4;

    for (int kt = 0; kt < 512; kt += 16){
        float4 a0 = *(const float4*)(Abase + kt);
        float4 a1 = *(const float4*)(Abase + (size_t)64*512 + kt);
        float4 w0 = *(const float4*)(Wbase + kt);
        float4 w1 = *(const float4*)(Wbase + (size_t)64*512 + kt);
        __syncthreads();
        As[(lc4+0)*132 + lr0]      = a0.x; As[(lc4+1)*132 + lr0]      = a0.y;
        As[(lc4+2)*132 + lr0]      = a0.z; As[(lc4+3)*132 + lr0]      = a0.w;
        As[(lc4+0)*132 + lr0 + 64] = a1.x; As[(lc4+1)*132 + lr0 + 64] = a1.y;
        As[(lc4+2)*132 + lr0 + 64] = a1.z; As[(lc4+3)*132 + lr0 + 64] = a1.w;
        Bs[(lc4+0)*132 + lr0]      = w0.x; Bs[(lc4+1)*132 + lr0]      = w0.y;
        Bs[(lc4+2)*132 + lr0]      = w0.z; Bs[(lc4+3)*132 + lr0]      = w0.w;
        Bs[(lc4+0)*132 + lr0 + 64] = w1.x; Bs[(lc4+1)*132 + lr0 + 64] = w1.y;
        Bs[(lc4+2)*132 + lr0 + 64] = w1.z; Bs[(lc4+3)*132 + lr0 + 64] = w1.w;
        __syncthreads();
#pragma unroll
        for (int k = 0; k < 16; k++){
            float4 af0 = *(const float4*)&As[k*132 + ty*8];
            float4 af1 = *(const float4*)&As[k*132 + ty*8 + 4];
            float4 bf0 = *(const float4*)&Bs[k*132 + tx*8];
            float4 bf1 = *(const float4*)&Bs[k*132 + tx*8 + 4];
            float av[8] = {af0.x,af0.y,af0.z,af0.w,af1.x,af1.y,af1.z,af1.w};
            float bv[8] = {bf0.x,bf0.y,bf0.z,bf0.w,bf1.x,bf1.y,bf1.z,bf1.w};
#pragma unroll
            for (int i = 0; i < 8; i++)
#pragma unroll
                for (int j = 0; j < 8; j++)
                    acc[i][j] = fmaf(av[i], bv[j], acc[i][j]);
        }
    }

    float4 bb0 = *(const float4*)&bias[n0 + tx*8];
    float4 bb1 = *(const float4*)&bias[n0 + tx*8 + 4];
    float bj[8] = {bb0.x,bb0.y,bb0.z,bb0.w,bb1.x,bb1.y,bb1.z,bb1.w};
#pragma unroll
    for (int i = 0; i < 8; i++){
        int m = m0 + ty*8 + i;
        __nv_bfloat162 p[4];
        p[0] = __floats2bfloat162_rn(acc[i][0]+bj[0], acc[i][1]+bj[1]);
        p[1] = __floats2bfloat162_rn(acc[i][2]+bj[2], acc[i][3]+bj[3]);
        p[2] = __floats2bfloat162_rn(acc[i][4]+bj[4], acc[i][5]+bj[5]);
        p[3] = __floats2bfloat162_rn(acc[i][6]+bj[6], acc[i][7]+bj[7]);
        *(uint4*)&g_codm[(size_t)m*512 + n0 + tx*8] = *(uint4*)p;
    }
}

// ---------------- per-step kernel 1: skinny proj, weights read ONCE per step ----------------
// grid 128 x 256 thr. warp w of block g owns weight row g*8+w (rm rows 0..511, rr rows 512..1023);
// row held in registers, loop over all 32 batches.
__global__ __launch_bounds__(256) void step_proj(const float* __restrict__ rm_w,
                                                 const float* __restrict__ rm_b,
                                                 const float* __restrict__ rr_w,
                                                 const float* __restrict__ rr_b,
                                                 int t)
{
    const int lane = threadIdx.x & 31, warp = threadIdx.x >> 5;
    const int prow = blockIdx.x * 8 + warp;           // 0..1023
    const bool is_rm = (prow < 512);
    const int e = is_rm ? prow : prow - 512;
    const float* wrow = (is_rm ? rm_w : rr_w) + (size_t)e*512;
    float4 w0 = *(const float4*)(wrow + lane*4);
    float4 w1 = *(const float4*)(wrow + lane*4 + 128);
    float4 w2 = *(const float4*)(wrow + lane*4 + 256);
    float4 w3 = *(const float4*)(wrow + lane*4 + 384);
    const float bias = is_rm ? rm_b[e] : rr_b[e];

#pragma unroll 4
    for (int b = 0; b < BB; b++){
        const float* rb = g_r + b*512;
        float4 r0 = *(const float4*)(rb + lane*4);
        float4 r1 = *(const float4*)(rb + lane*4 + 128);
        float4 r2 = *(const float4*)(rb + lane*4 + 256);
        float4 r3 = *(const float4*)(rb + lane*4 + 384);
        float s = w0.x*r0.x + w0.y*r0.y + w0.z*r0.z + w0.w*r0.w
                + w1.x*r1.x + w1.y*r1.y + w1.z*r1.z + w1.w*r1.w
                + w2.x*r2.x + w2.y*r2.y + w2.z*r2.z + w2.w*r2.w
                + w3.x*r3.x + w3.y*r3.y + w3.z*r3.z + w3.w*r3.w;
        s = warp_sum(s);
        if (lane == 0){
            if (is_rm) g_add[b*512 + e] = s + bias + g_qm[(t*BB + b)*512 + e];
            else       g_trr[b*512 + e] = tanh_fast(s + bias);
        }
    }
}

// ---------------- per-step kernel 2: logits from bf16 codm ----------------
// 1024 blocks x 256 thr; add & ms_w staged in smem; warp per (b,s) row.
__global__ __launch_bounds__(256) void step_logits(const float* __restrict__ ms_w,
                                                   const float* __restrict__ ms_b){
    __shared__ __align__(16) float sadd[512];
    __shared__ __align__(16) float smw[512];
    int tid  = threadIdx.x, lane = tid & 31, warp = tid >> 5;
    int b    = blockIdx.x >> 5;
    int row  = blockIdx.x*8 + warp;
    sadd[tid]       = g_add[b*512 + tid];
    sadd[tid + 256] = g_add[b*512 + tid + 256];
    smw[tid]        = ms_w[tid];
    smw[tid + 256]  = ms_w[tid + 256];
    __syncthreads();
    const __nv_bfloat16* cd = g_codm + (size_t)row*512;
    float s = 0.f;
#pragma unroll
    for (int i = 0; i < 4; i++){
        int k = i*128 + lane*4;
        uint2 u = *(const uint2*)(cd + k);
        float2 c01 = __bfloat1622float2(*(const __nv_bfloat162*)&u.x);
        float2 c23 = __bfloat1622float2(*(const __nv_bfloat162*)&u.y);
        float4 a = *(const float4*)(sadd + k);
        float4 m = *(const float4*)(smw + k);
        s += tanh_mufu(c01.x + a.x) * m.x;
        s += tanh_mufu(c01.y + a.y) * m.y;
        s += tanh_mufu(c23.x + a.z) * m.z;
        s += tanh_mufu(c23.y + a.w) * m.w;
    }
    s = warp_sum(s);
    if (lane == 0) g_logits[row] = s + ms_b[0];
}

// ---------------- per-step kernel 3: softmax over S + weighted sum of co + trr ----------------
__global__ __launch_bounds__(256) void step_update(){
    __shared__ float sw[256];
    __shared__ float part[256];
    __shared__ float red[16];
    int b = blockIdx.x, ec = blockIdx.y, tid = threadIdx.x;
    int lane = tid & 31, warp = tid >> 5;

    float l = g_logits[b*256 + tid];
    float m = l;
#pragma unroll
    for (int o = 16; o; o >>= 1) m = fmaxf(m, __shfl_xor_sync(0xffffffffu, m, o));
    if (lane == 0) red[warp] = m;
    __syncthreads();
    float mx = red[0];
#pragma unroll
    for (int i = 1; i < 8; i++) mx = fmaxf(mx, red[i]);
    float ex = __expf(l - mx);
    float sm = warp_sum(ex);
    if (lane == 0) red[8 + warp] = sm;
    __syncthreads();
    float tot = red[8];
#pragma unroll
    for (int i = 9; i < 16; i++) tot += red[i];
    sw[tid] = ex * (1.0f / tot);
    __syncthreads();

    int e  = ec*64 + (tid & 63);
    int sq = tid >> 6;
    const float* cb = g_co + (size_t)(b*256 + sq*64)*512 + e;
    const float* wv = sw + sq*64;
    float acc = 0.f;
#pragma unroll 8
    for (int s = 0; s < 64; s++)
        acc = fmaf(wv[s], cb[(size_t)s*512], acc);
    part[tid] = acc;
    __syncthreads();
    if (tid < 64){
        int eo = ec*64 + tid;
        g_r[b*512 + eo] = part[tid] + part[tid+64] + part[tid+128] + part[tid+192]
                        + g_trr[b*512 + eo];
    }
}

// ---------------- final: g = rg(r) + qg(qh) ----------------
__global__ __launch_bounds__(256) void final_g(const float* __restrict__ rg_w,
                                               const float* __restrict__ rg_b,
                                               const float* __restrict__ qg_w,
                                               const float* __restrict__ qg_b,
                                               const float* __restrict__ qh,
                                               float* __restrict__ out)
{
    __shared__ __align__(16) float sr[512];
    __shared__ __align__(16) float sq[512];
    int bx  = blockIdx.x;
    int b   = bx >> 6, ec = bx & 63;
    int tid = threadIdx.x, lane = tid & 31, warp = tid >> 5;
    sr[tid]       = g_r[b*512 + tid];
    sr[tid + 256] = g_r[b*512 + tid + 256];
    sq[tid]       = qh[b*512 + tid];
    sq[tid + 256] = qh[b*512 + tid + 256];
    __syncthreads();
    int e = ec*8 + warp;
    const float* w1 = rg_w + e*512;
    const float* w2 = qg_w + e*512;
    float s = 0.f;
#pragma unroll
    for (int i = 0; i < 4; i++){
        int k = i*128 + lane*4;
        float4 a = *(const float4*)(w1 + k); float4 x = *(const float4*)(sr + k);
        float4 c = *(const float4*)(w2 + k); float4 y = *(const float4*)(sq + k);
        s += a.x*x.x + a.y*x.y + a.z*x.z + a.w*x.w;
        s += c.x*y.x + c.y*y.y + c.z*y.z + c.w*y.w;
    }
    s = warp_sum(s);
    if (lane == 0) out[b*512 + e] = s + rg_b[e] + qg_b[e];
}

// ---------------- host launch ----------------
extern "C" void kernel_launch(void* const* d_in, const int* in_sizes, int n_in,
                              void* d_out, int out_size)
{
    const float* ctx  = (const float*)d_in[0];
    const float* qout = (const float*)d_in[2];
    const float* qh   = (const float*)d_in[3];
    const float* img  = (const float*)d_in[4];
    const float* fc1w = (const float*)d_in[6];  const float* fc1b = (const float*)d_in[7];
    const float* fc2w = (const float*)d_in[8];  const float* fc2b = (const float*)d_in[9];
    const float* dmw  = (const float*)d_in[10]; const float* dmb  = (const float*)d_in[11];
    const float* msw  = (const float*)d_in[12]; const float* msb  = (const float*)d_in[13];
    const float* rmw  = (const float*)d_in[14]; const float* rmb  = (const float*)d_in[15];
    const float* qmw  = (const float*)d_in[16]; const float* qmb  = (const float*)d_in[17];
    const float* rrw  = (const float*)d_in[18]; const float* rrb  = (const float*)d_in[19];
    const float* rgw  = (const float*)d_in[20]; const float* rgb  = (const float*)d_in[21];
    const float* qgw  = (const float*)d_in[22]; const float* qgb  = (const float*)d_in[23];

    prep_small<<<64, 256>>>(fc1b, fc2b);

    // co (fused perm+concat GEMM) + qm GEMM in ONE launch
    gemm_A<<<352, 256>>>(ctx, img, fc1w, fc2w, qout, qmw, qmb);

    // codm(bf16) = co @ dm_w^T + dm_b
    sgemm_codm<<<dim3(4, 64), 256>>>(dmw, dmb);

    for (int t = 0; t < TT; t++){
        step_proj<<<128, 256>>>(rmw, rmb, rrw, rrb, t);
        step_logits<<<1024, 256>>>(msw, msb);
        step_update<<<dim3(32, 8), 256>>>();
    }

    final_g<<<2048, 256>>>(rgw, rgb, qgw, qgb, qh, (float*)d_out);
}

// round 5
// speedup vs baseline: 1.5840x; 1.5840x over previous
#include <cuda_runtime.h>
#include <cuda_bf16.h>
#include <math.h>

#define DD 512
#define SS 256
#define BB 32
#define TT 24
#define NROWS (BB*SS)   // 8192

// ---------------- device scratch (static: no runtime allocation) ----------------
__device__ float g_bcat[512];                      // fc1_b + fc2_b
__device__ float g_co[NROWS*512];
__device__ __nv_bfloat16 g_codm[NROWS*512];        // bf16: only feeds tanh()
__device__ float g_qm[TT*BB*512];                  // qm projection of all question steps
__device__ float g_r[BB*512];
__device__ float g_add[BB*512];
__device__ float g_trr[BB*512];
__device__ float g_logits[BB*SS];

// ---------------- helpers ----------------
__device__ __forceinline__ float tanh_fast(float x){
    float ax = fabsf(x);
    float e  = __expf(fminf(ax, 15.0f) * 2.0f);
    float t  = __fdividef(e - 1.0f, e + 1.0f);
    return copysignf(t, x);
}

__device__ __forceinline__ float tanh_mufu(float x){
    float y;
    asm("tanh.approx.f32 %0, %1;" : "=f"(y) : "f"(x));
    return y;
}

__device__ __forceinline__ float warp_sum(float v){
#pragma unroll
    for (int o = 16; o; o >>= 1) v += __shfl_xor_sync(0xffffffffu, v, o);
    return v;
}

// ---------------- tiny prep: bias concat + r zero ----------------
__global__ __launch_bounds__(256) void prep_small(const float* __restrict__ fc1b,
                                                  const float* __restrict__ fc2b){
    int v = blockIdx.x * 256 + threadIdx.x;     // 64 blocks = 16384 threads
    if (v < 512)    g_bcat[v] = fc1b[v] + fc2b[v];
    if (v < BB*512) g_r[v]    = 0.0f;
}

// ---------------- fused GEMM launch A ----------------
// blocks [0,256):  co = perm(ctx)@fc1^T + perm(img)@fc2^T + bcat   (128x128 tile, K=2x512)
// blocks [256,352): qm = qout@qm_w^T + qm_b                        (64x64 tile, K=512)
__global__ __launch_bounds__(256) void gemm_A(const float* __restrict__ ctx,
                                              const float* __restrict__ img,
                                              const float* __restrict__ fc1w,
                                              const float* __restrict__ fc2w,
                                              const float* __restrict__ qout,
                                              const float* __restrict__ qmw,
                                              const float* __restrict__ qmb)
{
    __shared__ __align__(16) float sh[16*132*2];
    const int bid = blockIdx.x;
    const int tid = threadIdx.x;

    if (bid < 256){
        float* As = sh;
        float* Bs = sh + 16*132;
        const int m0  = (bid >> 2) * 128;
        const int n0  = (bid & 3) * 128;
        const int tx  = tid & 15, ty = tid >> 4;
        const int lr0 = tid >> 2;
        const int lc4 = (tid & 3) * 4;

        const int r1 = m0 + lr0, r2 = r1 + 64;
        const int p1 = (r1 & 255)*32 + (r1 >> 8);
        const int p2 = (r2 & 255)*32 + (r2 >> 8);

        float acc[8][8] = {};

#pragma unroll 1
        for (int half = 0; half < 2; half++){
            const float* Asrc = half ? img  : ctx;
            const float* Wsrc = half ? fc2w : fc1w;
            const float* A1 = Asrc + (size_t)p1*512 + lc4;
            const float* A2 = Asrc + (size_t)p2*512 + lc4;
            const float* W1 = Wsrc + (size_t)(n0 + lr0)*512 + lc4;
            const float* W2 = Wsrc + (size_t)(n0 + lr0 + 64)*512 + lc4;
            for (int kt = 0; kt < 512; kt += 16){
                float4 a0 = *(const float4*)(A1 + kt);
                float4 a1 = *(const float4*)(A2 + kt);
                float4 w0 = *(const float4*)(W1 + kt);
                float4 w1 = *(const float4*)(W2 + kt);
                __syncthreads();
                As[(lc4+0)*132 + lr0]      = a0.x; As[(lc4+1)*132 + lr0]      = a0.y;
                As[(lc4+2)*132 + lr0]      = a0.z; As[(lc4+3)*132 + lr0]      = a0.w;
                As[(lc4+0)*132 + lr0 + 64] = a1.x; As[(lc4+1)*132 + lr0 + 64] = a1.y;
                As[(lc4+2)*132 + lr0 + 64] = a1.z; As[(lc4+3)*132 + lr0 + 64] = a1.w;
                Bs[(lc4+0)*132 + lr0]      = w0.x; Bs[(lc4+1)*132 + lr0]      = w0.y;
                Bs[(lc4+2)*132 + lr0]      = w0.z; Bs[(lc4+3)*132 + lr0]      = w0.w;
                Bs[(lc4+0)*132 + lr0 + 64] = w1.x; Bs[(lc4+1)*132 + lr0 + 64] = w1.y;
                Bs[(lc4+2)*132 + lr0 + 64] = w1.z; Bs[(lc4+3)*132 + lr0 + 64] = w1.w;
                __syncthreads();
#pragma unroll
                for (int k = 0; k < 16; k++){
                    float4 af0 = *(const float4*)&As[k*132 + ty*8];
                    float4 af1 = *(const float4*)&As[k*132 + ty*8 + 4];
                    float4 bf0 = *(const float4*)&Bs[k*132 + tx*8];
                    float4 bf1 = *(const float4*)&Bs[k*132 + tx*8 + 4];
                    float av[8] = {af0.x,af0.y,af0.z,af0.w,af1.x,af1.y,af1.z,af1.w};
                    float bv[8] = {bf0.x,bf0.y,bf0.z,bf0.w,bf1.x,bf1.y,bf1.z,bf1.w};
#pragma unroll
                    for (int i = 0; i < 8; i++)
#pragma unroll
                        for (int j = 0; j < 8; j++)
                            acc[i][j] = fmaf(av[i], bv[j], acc[i][j]);
                }
            }
        }

        float4 bb0 = *(const float4*)&g_bcat[n0 + tx*8];
        float4 bb1 = *(const float4*)&g_bcat[n0 + tx*8 + 4];
        float bj[8] = {bb0.x,bb0.y,bb0.z,bb0.w,bb1.x,bb1.y,bb1.z,bb1.w};
#pragma unroll
        for (int i = 0; i < 8; i++){
            int m = m0 + ty*8 + i;
            float4 o0 = make_float4(acc[i][0]+bj[0], acc[i][1]+bj[1],
                                    acc[i][2]+bj[2], acc[i][3]+bj[3]);
            float4 o1 = make_float4(acc[i][4]+bj[4], acc[i][5]+bj[5],
                                    acc[i][6]+bj[6], acc[i][7]+bj[7]);
            *(float4*)&g_co[(size_t)m*512 + n0 + tx*8]     = o0;
            *(float4*)&g_co[(size_t)m*512 + n0 + tx*8 + 4] = o1;
        }
    } else {
        // ---- qm: 64x64 tile ----
        float* As = sh;            // stride 68
        float* Bs = sh + 16*68;
        const int qid = bid - 256;            // 0..95
        const int m0  = (qid >> 3) * 64;      // 12 tiles over M=768
        const int n0  = (qid & 7) * 64;       // 8 tiles over N=512
        const int tx  = tid & 15, ty = tid >> 4;
        const int lr0 = tid >> 2;             // 0..63
        const int lc4 = (tid & 3) * 4;

        float acc[4][4] = {};
        const float* A1 = qout + (size_t)(m0 + lr0)*512 + lc4;
        const float* W1 = qmw  + (size_t)(n0 + lr0)*512 + lc4;

        for (int kt = 0; kt < 512; kt += 16){
            float4 a0 = *(const float4*)(A1 + kt);
            float4 w0 = *(const float4*)(W1 + kt);
            __syncthreads();
            As[(lc4+0)*68 + lr0] = a0.x; As[(lc4+1)*68 + lr0] = a0.y;
            As[(lc4+2)*68 + lr0] = a0.z; As[(lc4+3)*68 + lr0] = a0.w;
            Bs[(lc4+0)*68 + lr0] = w0.x; Bs[(lc4+1)*68 + lr0] = w0.y;
            Bs[(lc4+2)*68 + lr0] = w0.z; Bs[(lc4+3)*68 + lr0] = w0.w;
            __syncthreads();
#pragma unroll
            for (int k = 0; k < 16; k++){
                float4 av = *(const float4*)&As[k*68 + ty*4];
                float4 bv = *(const float4*)&Bs[k*68 + tx*4];
                float aa[4] = {av.x,av.y,av.z,av.w};
                float bb[4] = {bv.x,bv.y,bv.z,bv.w};
#pragma unroll
                for (int i = 0; i < 4; i++)
#pragma unroll
                    for (int j = 0; j < 4; j++)
                        acc[i][j] = fmaf(aa[i], bb[j], acc[i][j]);
            }
        }

        float4 bq = *(const float4*)&qmb[n0 + tx*4];
        float bj[4] = {bq.x,bq.y,bq.z,bq.w};
#pragma unroll
        for (int i = 0; i < 4; i++){
            int m = m0 + ty*4 + i;
            float4 o = make_float4(acc[i][0]+bj[0], acc[i][1]+bj[1],
                                   acc[i][2]+bj[2], acc[i][3]+bj[3]);
            *(float4*)&g_qm[(size_t)m*512 + n0 + tx*4] = o;
        }
    }
}

// ---------------- codm GEMM: codm(bf16) = co @ dm_w^T + dm_b ----------------
__global__ __launch_bounds__(256) void sgemm_codm(const float* __restrict__ W,
                                                  const float* __restrict__ bias)
{
    __shared__ __align__(16) float As[16*132];
    __shared__ __align__(16) float Bs[16*132];
    const int m0  = blockIdx.y * 128;
    const int n0  = blockIdx.x * 128;
    const int tid = threadIdx.x;
    const int tx  = tid & 15, ty = tid >> 4;
    const int lr0 = tid >> 2;
    const int lc4 = (tid & 3) * 4;

    float acc[8][8] = {};
    const float* Abase = g_co + (size_t)(m0 + lr0) * 512 + lc4;
    const float* Wbase = W    + (size_t)(n0 + lr0) * 512 + lc4;

    for (int kt = 0; kt < 512; kt += 16){
        float4 a0 = *(const float4*)(Abase + kt);
        float4 a1 = *(const float4*)(Abase + (size_t)64*512 + kt);
        float4 w0 = *(const float4*)(Wbase + kt);
        float4 w1 = *(const float4*)(Wbase + (size_t)64*512 + kt);
        __syncthreads();
        As[(lc4+0)*132 + lr0]      = a0.x; As[(lc4+1)*132 + lr0]      = a0.y;
        As[(lc4+2)*132 + lr0]      = a0.z; As[(lc4+3)*132 + lr0]      = a0.w;
        As[(lc4+0)*132 + lr0 + 64] = a1.x; As[(lc4+1)*132 + lr0 + 64] = a1.y;
        As[(lc4+2)*132 + lr0 + 64] = a1.z; As[(lc4+3)*132 + lr0 + 64] = a1.w;
        Bs[(lc4+0)*132 + lr0]      = w0.x; Bs[(lc4+1)*132 + lr0]      = w0.y;
        Bs[(lc4+2)*132 + lr0]      = w0.z; Bs[(lc4+3)*132 + lr0]      = w0.w;
        Bs[(lc4+0)*132 + lr0 + 64] = w1.x; Bs[(lc4+1)*132 + lr0 + 64] = w1.y;
        Bs[(lc4+2)*132 + lr0 + 64] = w1.z; Bs[(lc4+3)*132 + lr0 + 64] = w1.w;
        __syncthreads();
#pragma unroll
        for (int k = 0; k < 16; k++){
            float4 af0 = *(const float4*)&As[k*132 + ty*8];
            float4 af1 = *(const float4*)&As[k*132 + ty*8 + 4];
            float4 bf0 = *(const float4*)&Bs[k*132 + tx*8];
            float4 bf1 = *(const float4*)&Bs[k*132 + tx*8 + 4];
            float av[8] = {af0.x,af0.y,af0.z,af0.w,af1.x,af1.y,af1.z,af1.w};
            float bv[8] = {bf0.x,bf0.y,bf0.z,bf0.w,bf1.x,bf1.y,bf1.z,bf1.w};
#pragma unroll
            for (int i = 0; i < 8; i++)
#pragma unroll
                for (int j = 0; j < 8; j++)
                    acc[i][j] = fmaf(av[i], bv[j], acc[i][j]);
        }
    }

    float4 bb0 = *(const float4*)&bias[n0 + tx*8];
    float4 bb1 = *(const float4*)&bias[n0 + tx*8 + 4];
    float bj[8] = {bb0.x,bb0.y,bb0.z,bb0.w,bb1.x,bb1.y,bb1.z,bb1.w};
#pragma unroll
    for (int i = 0; i < 8; i++){
        int m = m0 + ty*8 + i;
        __nv_bfloat162 p[4];
        p[0] = __floats2bfloat162_rn(acc[i][0]+bj[0], acc[i][1]+bj[1]);
        p[1] = __floats2bfloat162_rn(acc[i][2]+bj[2], acc[i][3]+bj[3]);
        p[2] = __floats2bfloat162_rn(acc[i][4]+bj[4], acc[i][5]+bj[5]);
        p[3] = __floats2bfloat162_rn(acc[i][6]+bj[6], acc[i][7]+bj[7]);
        *(uint4*)&g_codm[(size_t)m*512 + n0 + tx*8] = *(uint4*)p;
    }
}

// ---------------- per-step kernel 1: proj over 4-batch groups ----------------
// 1024 blocks = mat(2) x bgrp(8) x ec(64), 256 thr. Block stages 4 batches of r
// in smem; warp w owns weight row ec*8+w, reduces 4 batches. Weight traffic 16MB/step.
__global__ __launch_bounds__(256) void step_proj(const float* __restrict__ rm_w,
                                                 const float* __restrict__ rm_b,
                                                 const float* __restrict__ rr_w,
                                                 const float* __restrict__ rr_b,
                                                 int t)
{
    __shared__ __align__(16) float sr[4*512];
    const int bx   = blockIdx.x;
    const int mat  = bx >> 9;                 // 0: rm, 1: rr
    const int bg   = (bx >> 6) & 7;           // 4-batch group
    const int ec   = bx & 63;
    const int tid  = threadIdx.x, lane = tid & 31, warp = tid >> 5;

    // stage r for batches 4*bg .. 4*bg+3 (2048 floats = 512 float4)
#pragma unroll
    for (int i = 0; i < 2; i++)
        ((float4*)sr)[tid + i*256] = ((const float4*)(g_r + bg*4*512))[tid + i*256];
    __syncthreads();

    const int e = ec*8 + warp;
    const float* wrow = (mat ? rr_w : rm_w) + (size_t)e*512;
    float4 w0 = *(const float4*)(wrow + lane*4);
    float4 w1 = *(const float4*)(wrow + lane*4 + 128);
    float4 w2 = *(const float4*)(wrow + lane*4 + 256);
    float4 w3 = *(const float4*)(wrow + lane*4 + 384);
    const float bias = mat ? rr_b[e] : rm_b[e];

#pragma unroll
    for (int bl = 0; bl < 4; bl++){
        const float* rb = sr + bl*512;
        float4 r0 = *(const float4*)(rb + lane*4);
        float4 r1 = *(const float4*)(rb + lane*4 + 128);
        float4 r2 = *(const float4*)(rb + lane*4 + 256);
        float4 r3 = *(const float4*)(rb + lane*4 + 384);
        float s = w0.x*r0.x + w0.y*r0.y + w0.z*r0.z + w0.w*r0.w
                + w1.x*r1.x + w1.y*r1.y + w1.z*r1.z + w1.w*r1.w
                + w2.x*r2.x + w2.y*r2.y + w2.z*r2.z + w2.w*r2.w
                + w3.x*r3.x + w3.y*r3.y + w3.z*r3.z + w3.w*r3.w;
        s = warp_sum(s);
        if (lane == 0){
            int b = bg*4 + bl;
            if (mat == 0) g_add[b*512 + e] = s + bias + g_qm[(t*BB + b)*512 + e];
            else          g_trr[b*512 + e] = tanh_fast(s + bias);
        }
    }
}

// ---------------- per-step kernel 2: logits from bf16 codm ----------------
// 1024 blocks x 256 thr; add & ms_w staged in smem; warp per (b,s) row.
__global__ __launch_bounds__(256) void step_logits(const float* __restrict__ ms_w,
                                                   const float* __restrict__ ms_b){
    __shared__ __align__(16) float sadd[512];
    __shared__ __align__(16) float smw[512];
    int tid  = threadIdx.x, lane = tid & 31, warp = tid >> 5;
    int b    = blockIdx.x >> 5;
    int row  = blockIdx.x*8 + warp;
    sadd[tid]       = g_add[b*512 + tid];
    sadd[tid + 256] = g_add[b*512 + tid + 256];
    smw[tid]        = ms_w[tid];
    smw[tid + 256]  = ms_w[tid + 256];
    __syncthreads();
    const __nv_bfloat16* cd = g_codm + (size_t)row*512;
    float s = 0.f;
#pragma unroll
    for (int i = 0; i < 4; i++){
        int k = i*128 + lane*4;
        uint2 u = *(const uint2*)(cd + k);
        float2 c01 = __bfloat1622float2(*(const __nv_bfloat162*)&u.x);
        float2 c23 = __bfloat1622float2(*(const __nv_bfloat162*)&u.y);
        float4 a = *(const float4*)(sadd + k);
        float4 m = *(const float4*)(smw + k);
        s += tanh_mufu(c01.x + a.x) * m.x;
        s += tanh_mufu(c01.y + a.y) * m.y;
        s += tanh_mufu(c23.x + a.z) * m.z;
        s += tanh_mufu(c23.y + a.w) * m.w;
    }
    s = warp_sum(s);
    if (lane == 0) g_logits[row] = s + ms_b[0];
}

// ---------------- per-step kernel 3: softmax over S + weighted sum of co + trr ----------------
__global__ __launch_bounds__(256) void step_update(){
    __shared__ float sw[256];
    __shared__ float part[256];
    __shared__ float red[16];
    int b = blockIdx.x, ec = blockIdx.y, tid = threadIdx.x;
    int lane = tid & 31, warp = tid >> 5;

    float l = g_logits[b*256 + tid];
    float m = l;
#pragma unroll
    for (int o = 16; o; o >>= 1) m = fmaxf(m, __shfl_xor_sync(0xffffffffu, m, o));
    if (lane == 0) red[warp] = m;
    __syncthreads();
    float mx = red[0];
#pragma unroll
    for (int i = 1; i < 8; i++) mx = fmaxf(mx, red[i]);
    float ex = __expf(l - mx);
    float sm = warp_sum(ex);
    if (lane == 0) red[8 + warp] = sm;
    __syncthreads();
    float tot = red[8];
#pragma unroll
    for (int i = 9; i < 16; i++) tot += red[i];
    sw[tid] = ex * (1.0f / tot);
    __syncthreads();

    int e  = ec*64 + (tid & 63);
    int sq = tid >> 6;
    const float* cb = g_co + (size_t)(b*256 + sq*64)*512 + e;
    const float* wv = sw + sq*64;
    float acc = 0.f;
#pragma unroll 8
    for (int s = 0; s < 64; s++)
        acc = fmaf(wv[s], cb[(size_t)s*512], acc);
    part[tid] = acc;
    __syncthreads();
    if (tid < 64){
        int eo = ec*64 + tid;
        g_r[b*512 + eo] = part[tid] + part[tid+64] + part[tid+128] + part[tid+192]
                        + g_trr[b*512 + eo];
    }
}

// ---------------- final: g = rg(r) + qg(qh) ----------------
__global__ __launch_bounds__(256) void final_g(const float* __restrict__ rg_w,
                                               const float* __restrict__ rg_b,
                                               const float* __restrict__ qg_w,
                                               const float* __restrict__ qg_b,
                                               const float* __restrict__ qh,
                                               float* __restrict__ out)
{
    __shared__ __align__(16) float sr[512];
    __shared__ __align__(16) float sq[512];
    int bx  = blockIdx.x;
    int b   = bx >> 6, ec = bx & 63;
    int tid = threadIdx.x, lane = tid & 31, warp = tid >> 5;
    sr[tid]       = g_r[b*512 + tid];
    sr[tid + 256] = g_r[b*512 + tid + 256];
    sq[tid]       = qh[b*512 + tid];
    sq[tid + 256] = qh[b*512 + tid + 256];
    __syncthreads();
    int e = ec*8 + warp;
    const float* w1 = rg_w + e*512;
    const float* w2 = qg_w + e*512;
    float s = 0.f;
#pragma unroll
    for (int i = 0; i < 4; i++){
        int k = i*128 + lane*4;
        float4 a = *(const float4*)(w1 + k); float4 x = *(const float4*)(sr + k);
        float4 c = *(const float4*)(w2 + k); float4 y = *(const float4*)(sq + k);
        s += a.x*x.x + a.y*x.y + a.z*x.z + a.w*x.w;
        s += c.x*y.x + c.y*y.y + c.z*y.z + c.w*y.w;
    }
    s = warp_sum(s);
    if (lane == 0) out[b*512 + e] = s + rg_b[e] + qg_b[e];
}

// ---------------- host launch ----------------
extern "C" void kernel_launch(void* const* d_in, const int* in_sizes, int n_in,
                              void* d_out, int out_size)
{
    const float* ctx  = (const float*)d_in[0];
    const float* qout = (const float*)d_in[2];
    const float* qh   = (const float*)d_in[3];
    const float* img  = (const float*)d_in[4];
    const float* fc1w = (const float*)d_in[6];  const float* fc1b = (const float*)d_in[7];
    const float* fc2w = (const float*)d_in[8];  const float* fc2b = (const float*)d_in[9];
    const float* dmw  = (const float*)d_in[10]; const float* dmb  = (const float*)d_in[11];
    const float* msw  = (const float*)d_in[12]; const float* msb  = (const float*)d_in[13];
    const float* rmw  = (const float*)d_in[14]; const float* rmb  = (const float*)d_in[15];
    const float* qmw  = (const float*)d_in[16]; const float* qmb  = (const float*)d_in[17];
    const float* rrw  = (const float*)d_in[18]; const float* rrb  = (const float*)d_in[19];
    const float* rgw  = (const float*)d_in[20]; const float* rgb  = (const float*)d_in[21];
    const float* qgw  = (const float*)d_in[22]; const float* qgb  = (const float*)d_in[23];

    prep_small<<<64, 256>>>(fc1b, fc2b);

    // co (fused perm+concat GEMM) + qm GEMM in ONE launch
    gemm_A<<<352, 256>>>(ctx, img, fc1w, fc2w, qout, qmw, qmb);

    // codm(bf16) = co @ dm_w^T + dm_b
    sgemm_codm<<<dim3(4, 64), 256>>>(dmw, dmb);

    for (int t = 0; t < TT; t++){
        step_proj<<<1024, 256>>>(rmw, rmb, rrw, rrb, t);
        step_logits<<<1024, 256>>>(msw, msb);
        step_update<<<dim3(32, 8), 256>>>();
    }

    final_g<<<2048, 256>>>(rgw, rgb, qgw, qgb, qh, (float*)d_out);
}

// round 7
// speedup vs baseline: 1.6289x; 1.0283x over previous
#include <cuda_runtime.h>
#include <cuda_bf16.h>
#include <cstdint>
#include <math.h>

#define DD 512
#define SS 256
#define BB 32
#define TT 24
#define NROWS (BB*SS)   // 8192

// ---------------- device scratch (static: no runtime allocation) ----------------
__device__ float g_bcat[512];                      // fc1_b + fc2_b
__device__ float g_co[NROWS*512];
__device__ __nv_bfloat16 g_codm[NROWS*512];        // bf16: only feeds tanh()
__device__ float g_qm[TT*BB*512];                  // qm projection of all question steps
__device__ float g_r[BB*512];
__device__ float g_add[BB*512];
__device__ float g_trr[BB*512];

// ---------------- helpers ----------------
__device__ __forceinline__ float tanh_fast(float x){
    float ax = fabsf(x);
    float e  = __expf(fminf(ax, 15.0f) * 2.0f);
    float t  = __fdividef(e - 1.0f, e + 1.0f);
    return copysignf(t, x);
}

__device__ __forceinline__ float tanh_mufu(float x){
    float y;
    asm("tanh.approx.f32 %0, %1;" : "=f"(y) : "f"(x));
    return y;
}

__device__ __forceinline__ float warp_sum(float v){
#pragma unroll
    for (int o = 16; o; o >>= 1) v += __shfl_xor_sync(0xffffffffu, v, o);
    return v;
}

__device__ __forceinline__ unsigned int s2u(const void* p){
    unsigned int a;
    asm("{ .reg .u64 t; cvta.to.shared.u64 t, %1; cvt.u32.u64 %0, t; }" : "=r"(a) : "l"(p));
    return a;
}

__device__ __forceinline__ float dsmem_ld(unsigned int saddr, unsigned int rank){
    unsigned int ra; float v;
    asm("mapa.shared::cluster.u32 %0, %1, %2;" : "=r"(ra) : "r"(saddr), "r"(rank));
    asm("ld.shared::cluster.f32 %0, [%1];" : "=f"(v) : "r"(ra));
    return v;
}

#define CLUSTER_SYNC() do{ \
    asm volatile("barrier.cluster.arrive.aligned;" ::: "memory"); \
    asm volatile("barrier.cluster.wait.aligned;"   ::: "memory"); }while(0)

// ---------------- GEMM building blocks (128x128 tile, BK=16, 256 thr) ----------------
__device__ __forceinline__ void sts16(float* As, float* Bs, int lr0, int lc4,
                                      float4 a0, float4 a1, float4 w0, float4 w1){
    As[(lc4+0)*132 + lr0]      = a0.x; As[(lc4+1)*132 + lr0]      = a0.y;
    As[(lc4+2)*132 + lr0]      = a0.z; As[(lc4+3)*132 + lr0]      = a0.w;
    As[(lc4+0)*132 + lr0 + 64] = a1.x; As[(lc4+1)*132 + lr0 + 64] = a1.y;
    As[(lc4+2)*132 + lr0 + 64] = a1.z; As[(lc4+3)*132 + lr0 + 64] = a1.w;
    Bs[(lc4+0)*132 + lr0]      = w0.x; Bs[(lc4+1)*132 + lr0]      = w0.y;
    Bs[(lc4+2)*132 + lr0]      = w0.z; Bs[(lc4+3)*132 + lr0]      = w0.w;
    Bs[(lc4+0)*132 + lr0 + 64] = w1.x; Bs[(lc4+1)*132 + lr0 + 64] = w1.y;
    Bs[(lc4+2)*132 + lr0 + 64] = w1.z; Bs[(lc4+3)*132 + lr0 + 64] = w1.w;
}

__device__ __forceinline__ void mm16(const float* As, const float* Bs,
                                     float acc[8][8], int tx, int ty){
#pragma unroll
    for (int k = 0; k < 16; k++){
        float4 af0 = *(const float4*)&As[k*132 + ty*8];
        float4 af1 = *(const float4*)&As[k*132 + ty*8 + 4];
        float4 bf0 = *(const float4*)&Bs[k*132 + tx*8];
        float4 bf1 = *(const float4*)&Bs[k*132 + tx*8 + 4];
        float av[8] = {af0.x,af0.y,af0.z,af0.w,af1.x,af1.y,af1.z,af1.w};
        float bv[8] = {bf0.x,bf0.y,bf0.z,bf0.w,bf1.x,bf1.y,bf1.z,bf1.w};
#pragma unroll
        for (int i = 0; i < 8; i++)
#pragma unroll
            for (int j = 0; j < 8; j++)
                acc[i][j] = fmaf(av[i], bv[j], acc[i][j]);
    }
}

// ---------------- tiny prep: bias concat + r zero ----------------
__global__ __launch_bounds__(256) void prep_small(const float* __restrict__ fc1b,
                                                  const float* __restrict__ fc2b){
    int v = blockIdx.x * 256 + threadIdx.x;
    if (v < 512)    g_bcat[v] = fc1b[v] + fc2b[v];
    if (v < BB*512) g_r[v]    = 0.0f;
}

// ---------------- fused GEMM launch A (double-buffered pipeline) ----------------
// blocks [0,256):  co = perm(ctx)@fc1^T + perm(img)@fc2^T + bcat
// blocks [256,352): qm = qout@qm_w^T + qm_b  (64x64 tile)
__global__ __launch_bounds__(256) void gemm_A(const float* __restrict__ ctx,
                                              const float* __restrict__ img,
                                              const float* __restrict__ fc1w,
                                              const float* __restrict__ fc2w,
                                              const float* __restrict__ qout,
                                              const float* __restrict__ qmw,
                                              const float* __restrict__ qmb)
{
    __shared__ __align__(16) float sh[4*2112];   // As0,Bs0,As1,Bs1
    const int bid = blockIdx.x;
    const int tid = threadIdx.x;

    if (bid < 256){
        const int m0  = (bid >> 2) * 128;
        const int n0  = (bid & 3) * 128;
        const int tx  = tid & 15, ty = tid >> 4;
        const int lr0 = tid >> 2;
        const int lc4 = (tid & 3) * 4;

        const int r1 = m0 + lr0, r2 = r1 + 64;
        const int p1 = (r1 & 255)*32 + (r1 >> 8);
        const int p2 = (r2 & 255)*32 + (r2 >> 8);

        const float* A1h[2] = { ctx + (size_t)p1*512 + lc4,  img + (size_t)p1*512 + lc4 };
        const float* A2h[2] = { ctx + (size_t)p2*512 + lc4,  img + (size_t)p2*512 + lc4 };
        const float* W1h[2] = { fc1w + (size_t)(n0+lr0)*512 + lc4,
                                fc2w + (size_t)(n0+lr0)*512 + lc4 };
        const float* W2h[2] = { fc1w + (size_t)(n0+lr0+64)*512 + lc4,
                                fc2w + (size_t)(n0+lr0+64)*512 + lc4 };

        float acc[8][8] = {};
        float4 a0, a1, w0, w1;

        // prologue: tile 0
        a0 = *(const float4*)A1h[0]; a1 = *(const float4*)A2h[0];
        w0 = *(const float4*)W1h[0]; w1 = *(const float4*)W2h[0];
        sts16(sh, sh + 2112, lr0, lc4, a0, a1, w0, w1);
        __syncthreads();

#pragma unroll 1
        for (int it = 0; it < 64; it++){
            const bool has = (it + 1 < 64);
            if (has){
                const int h  = (it+1) >> 5;
                const int kt = ((it+1) & 31) * 16;
                a0 = *(const float4*)((h ? A1h[1] : A1h[0]) + kt);
                a1 = *(const float4*)((h ? A2h[1] : A2h[0]) + kt);
                w0 = *(const float4*)((h ? W1h[1] : W1h[0]) + kt);
                w1 = *(const float4*)((h ? W2h[1] : W2h[0]) + kt);
            }
            const int cur = (it & 1) * 4224;
            mm16(sh + cur, sh + cur + 2112, acc, tx, ty);
            if (has){
                const int nxt = ((it+1) & 1) * 4224;
                sts16(sh + nxt, sh + nxt + 2112, lr0, lc4, a0, a1, w0, w1);
            }
            __syncthreads();
        }

        float4 bb0 = *(const float4*)&g_bcat[n0 + tx*8];
        float4 bb1 = *(const float4*)&g_bcat[n0 + tx*8 + 4];
        float bj[8] = {bb0.x,bb0.y,bb0.z,bb0.w,bb1.x,bb1.y,bb1.z,bb1.w};
#pragma unroll
        for (int i = 0; i < 8; i++){
            int m = m0 + ty*8 + i;
            float4 o0 = make_float4(acc[i][0]+bj[0], acc[i][1]+bj[1],
                                    acc[i][2]+bj[2], acc[i][3]+bj[3]);
            float4 o1 = make_float4(acc[i][4]+bj[4], acc[i][5]+bj[5],
                                    acc[i][6]+bj[6], acc[i][7]+bj[7]);
            *(float4*)&g_co[(size_t)m*512 + n0 + tx*8]     = o0;
            *(float4*)&g_co[(size_t)m*512 + n0 + tx*8 + 4] = o1;
        }
    } else {
        // ---- qm: 64x64 tile (small, unpipelined) ----
        float* As = sh;            // stride 68
        float* Bs = sh + 16*68;
        const int qid = bid - 256;
        const int m0  = (qid >> 3) * 64;
        const int n0  = (qid & 7) * 64;
        const int tx  = tid & 15, ty = tid >> 4;
        const int lr0 = tid >> 2;
        const int lc4 = (tid & 3) * 4;

        float acc[4][4] = {};
        const float* A1 = qout + (size_t)(m0 + lr0)*512 + lc4;
        const float* W1 = qmw  + (size_t)(n0 + lr0)*512 + lc4;

        for (int kt = 0; kt < 512; kt += 16){
            float4 a0 = *(const float4*)(A1 + kt);
            float4 w0 = *(const float4*)(W1 + kt);
            __syncthreads();
            As[(lc4+0)*68 + lr0] = a0.x; As[(lc4+1)*68 + lr0] = a0.y;
            As[(lc4+2)*68 + lr0] = a0.z; As[(lc4+3)*68 + lr0] = a0.w;
            Bs[(lc4+0)*68 + lr0] = w0.x; Bs[(lc4+1)*68 + lr0] = w0.y;
            Bs[(lc4+2)*68 + lr0] = w0.z; Bs[(lc4+3)*68 + lr0] = w0.w;
            __syncthreads();
#pragma unroll
            for (int k = 0; k < 16; k++){
                float4 av = *(const float4*)&As[k*68 + ty*4];
                float4 bv = *(const float4*)&Bs[k*68 + tx*4];
                float aa[4] = {av.x,av.y,av.z,av.w};
                float bb[4] = {bv.x,bv.y,bv.z,bv.w};
#pragma unroll
                for (int i = 0; i < 4; i++)
#pragma unroll
                    for (int j = 0; j < 4; j++)
                        acc[i][j] = fmaf(aa[i], bb[j], acc[i][j]);
            }
        }

        float4 bq = *(const float4*)&qmb[n0 + tx*4];
        float bj[4] = {bq.x,bq.y,bq.z,bq.w};
#pragma unroll
        for (int i = 0; i < 4; i++){
            int m = m0 + ty*4 + i;
            float4 o = make_float4(acc[i][0]+bj[0], acc[i][1]+bj[1],
                                   acc[i][2]+bj[2], acc[i][3]+bj[3]);
            *(float4*)&g_qm[(size_t)m*512 + n0 + tx*4] = o;
        }
    }
}

// ---------------- codm GEMM (double-buffered): codm(bf16) = co @ dm_w^T + dm_b ----------------
__global__ __launch_bounds__(256) void sgemm_codm(const float* __restrict__ W,
                                                  const float* __restrict__ bias)
{
    __shared__ __align__(16) float sh[4*2112];
    const int m0  = blockIdx.y * 128;
    const int n0  = blockIdx.x * 128;
    const int tid = threadIdx.x;
    const int tx  = tid & 15, ty = tid >> 4;
    const int lr0 = tid >> 2;
    const int lc4 = (tid & 3) * 4;

    const float* A1 = g_co + (size_t)(m0 + lr0) * 512 + lc4;
    const float* A2 = A1 + (size_t)64*512;
    const float* W1 = W + (size_t)(n0 + lr0) * 512 + lc4;
    const float* W2 = W1 + (size_t)64*512;

    float acc[8][8] = {};
    float4 a0 = *(const float4*)A1;
    float4 a1 = *(const float4*)A2;
    float4 w0 = *(const float4*)W1;
    float4 w1 = *(const float4*)W2;
    sts16(sh, sh + 2112, lr0, lc4, a0, a1, w0, w1);
    __syncthreads();

#pragma unroll 1
    for (int it = 0; it < 32; it++){
        const bool has = (it + 1 < 32);
        if (has){
            const int kt = (it+1) * 16;
            a0 = *(const float4*)(A1 + kt); a1 = *(const float4*)(A2 + kt);
            w0 = *(const float4*)(W1 + kt); w1 = *(const float4*)(W2 + kt);
        }
        const int cur = (it & 1) * 4224;
        mm16(sh + cur, sh + cur + 2112, acc, tx, ty);
        if (has){
            const int nxt = ((it+1) & 1) * 4224;
            sts16(sh + nxt, sh + nxt + 2112, lr0, lc4, a0, a1, w0, w1);
        }
        __syncthreads();
    }

    float4 bb0 = *(const float4*)&bias[n0 + tx*8];
    float4 bb1 = *(const float4*)&bias[n0 + tx*8 + 4];
    float bj[8] = {bb0.x,bb0.y,bb0.z,bb0.w,bb1.x,bb1.y,bb1.z,bb1.w};
#pragma unroll
    for (int i = 0; i < 8; i++){
        int m = m0 + ty*8 + i;
        __nv_bfloat162 p[4];
        p[0] = __floats2bfloat162_rn(acc[i][0]+bj[0], acc[i][1]+bj[1]);
        p[1] = __floats2bfloat162_rn(acc[i][2]+bj[2], acc[i][3]+bj[3]);
        p[2] = __floats2bfloat162_rn(acc[i][4]+bj[4], acc[i][5]+bj[5]);
        p[3] = __floats2bfloat162_rn(acc[i][6]+bj[6], acc[i][7]+bj[7]);
        *(uint4*)&g_codm[(size_t)m*512 + n0 + tx*8] = *(uint4*)p;
    }
}

// ---------------- per-step kernel 1: proj (weight LDGs prefetched before r staging) ----------------
__global__ __launch_bounds__(256) void step_proj(const float* __restrict__ rm_w,
                                                 const float* __restrict__ rm_b,
                                                 const float* __restrict__ rr_w,
                                                 const float* __restrict__ rr_b,
                                                 int t)
{
    __shared__ __align__(16) float sr[4*512];
    const int bx   = blockIdx.x;
    const int mat  = bx >> 9;                 // 0: rm, 1: rr
    const int bg   = (bx >> 6) & 7;           // 4-batch group
    const int ec   = bx & 63;
    const int tid  = threadIdx.x, lane = tid & 31, warp = tid >> 5;

    // issue weight LDGs FIRST so their latency hides under the r staging + barrier
    const int e = ec*8 + warp;
    const float* wrow = (mat ? rr_w : rm_w) + (size_t)e*512;
    float4 w0 = *(const float4*)(wrow + lane*4);
    float4 w1 = *(const float4*)(wrow + lane*4 + 128);
    float4 w2 = *(const float4*)(wrow + lane*4 + 256);
    float4 w3 = *(const float4*)(wrow + lane*4 + 384);
    const float bias = mat ? rr_b[e] : rm_b[e];

    // stage r for batches 4*bg .. 4*bg+3
#pragma unroll
    for (int i = 0; i < 2; i++)
        ((float4*)sr)[tid + i*256] = ((const float4*)(g_r + bg*4*512))[tid + i*256];
    __syncthreads();

#pragma unroll
    for (int bl = 0; bl < 4; bl++){
        const float* rb = sr + bl*512;
        float4 r0 = *(const float4*)(rb + lane*4);
        float4 r1 = *(const float4*)(rb + lane*4 + 128);
        float4 r2 = *(const float4*)(rb + lane*4 + 256);
        float4 r3 = *(const float4*)(rb + lane*4 + 384);
        float s = w0.x*r0.x + w0.y*r0.y + w0.z*r0.z + w0.w*r0.w
                + w1.x*r1.x + w1.y*r1.y + w1.z*r1.z + w1.w*r1.w
                + w2.x*r2.x + w2.y*r2.y + w2.z*r2.z + w2.w*r2.w
                + w3.x*r3.x + w3.y*r3.y + w3.z*r3.z + w3.w*r3.w;
        s = warp_sum(s);
        if (lane == 0){
            int b = bg*4 + bl;
            if (mat == 0) g_add[b*512 + e] = s + bias + g_qm[(t*BB + b)*512 + e];
            else          g_trr[b*512 + e] = tanh_fast(s + bias);
        }
    }
}

// ---------------- per-step kernel 2: FUSED logits + softmax + update (8-CTA cluster per batch) ----------------
// grid 256 = 32 batches x 8-CTA clusters. CTA rank computes 32 logits rows,
// exchanges via DSMEM, full softmax redundantly, then its 64-e slice of the update.
__global__ __launch_bounds__(256) __cluster_dims__(8, 1, 1)
void step_fused(const float* __restrict__ ms_w, const float* __restrict__ ms_b)
{
    __shared__ __align__(16) float sadd[512];
    __shared__ __align__(16) float smw[512];
    __shared__ __align__(16) float slog[32];
    __shared__ float ssw[256];
    __shared__ float part[256];
    __shared__ float red[16];

    const int tid = threadIdx.x, lane = tid & 31, warp = tid >> 5;
    unsigned int rank; asm("mov.u32 %0, %%cluster_ctarank;" : "=r"(rank));
    const int b = blockIdx.x >> 3;
    const float msb0 = ms_b[0];

    sadd[tid]       = g_add[b*512 + tid];
    sadd[tid + 256] = g_add[b*512 + tid + 256];
    smw[tid]        = ms_w[tid];
    smw[tid + 256]  = ms_w[tid + 256];
    __syncthreads();

    // ---- 32 logits rows: warp w computes local rows w*4..w*4+3 ----
    float acc4[4] = {0.f, 0.f, 0.f, 0.f};
    const __nv_bfloat16* cd0 = g_codm + (size_t)(b*256 + (int)rank*32 + warp*4)*512;
#pragma unroll
    for (int rw = 0; rw < 4; rw++){
        const __nv_bfloat16* cd = cd0 + (size_t)rw*512;
        float s = 0.f;
#pragma unroll
        for (int i = 0; i < 4; i++){
            int k = i*128 + lane*4;
            uint2 u = *(const uint2*)(cd + k);
            float2 c01 = __bfloat1622float2(*(const __nv_bfloat162*)&u.x);
            float2 c23 = __bfloat1622float2(*(const __nv_bfloat162*)&u.y);
            float4 a = *(const float4*)(sadd + k);
            float4 m = *(const float4*)(smw + k);
            s += tanh_mufu(c01.x + a.x) * m.x;
            s += tanh_mufu(c01.y + a.y) * m.y;
            s += tanh_mufu(c23.x + a.z) * m.z;
            s += tanh_mufu(c23.y + a.w) * m.w;
        }
        acc4[rw] = s;
    }
#pragma unroll
    for (int rw = 0; rw < 4; rw++){
        float v = warp_sum(acc4[rw]);
        if (lane == 0) slog[warp*4 + rw] = v + msb0;
    }
    __syncthreads();
    CLUSTER_SYNC();                   // slog visible cluster-wide

    // ---- gather all 256 logits via DSMEM ----
    float l = dsmem_ld(s2u(&slog[tid & 31]), (unsigned int)(tid >> 5));

    // ---- softmax over 256 (redundant per CTA) ----
    float m = l;
#pragma unroll
    for (int o = 16; o; o >>= 1) m = fmaxf(m, __shfl_xor_sync(0xffffffffu, m, o));
    if (lane == 0) red[warp] = m;
    __syncthreads();
    float mx = red[0];
#pragma unroll
    for (int i = 1; i < 8; i++) mx = fmaxf(mx, red[i]);
    float ex = __expf(l - mx);
    float sm = warp_sum(ex);
    if (lane == 0) red[8 + warp] = sm;
    __syncthreads();
    float tot = red[8];
#pragma unroll
    for (int i = 9; i < 16; i++) tot += red[i];
    ssw[tid] = ex * (1.0f / tot);
    __syncthreads();

    // ---- update: e-slice [rank*64, rank*64+64), S split 4-way per thread ----
    int e  = (int)rank*64 + (tid & 63);
    int sq = tid >> 6;
    const float* cb = g_co + (size_t)(b*256 + sq*64)*512 + e;
    const float* wv = ssw + sq*64;
    float acc = 0.f;
#pragma unroll 8
    for (int s = 0; s < 64; s++)
        acc = fmaf(wv[s], cb[(size_t)s*512], acc);
    part[tid] = acc;
    __syncthreads();
    if (tid < 64){
        int eo = (int)rank*64 + tid;
        g_r[b*512 + eo] = part[tid] + part[tid+64] + part[tid+128] + part[tid+192]
                        + g_trr[b*512 + eo];
    }
    CLUSTER_SYNC();                   // no CTA exits while peers may still read its slog
}

// ---------------- final: g = rg(r) + qg(qh) ----------------
__global__ __launch_bounds__(256) void final_g(const float* __restrict__ rg_w,
                                               const float* __restrict__ rg_b,
                                               const float* __restrict__ qg_w,
                                               const float* __restrict__ qg_b,
                                               const float* __restrict__ qh,
                                               float* __restrict__ out)
{
    __shared__ __align__(16) float sr[512];
    __shared__ __align__(16) float sq[512];
    int bx  = blockIdx.x;
    int b   = bx >> 6, ec = bx & 63;
    int tid = threadIdx.x, lane = tid & 31, warp = tid >> 5;
    sr[tid]       = g_r[b*512 + tid];
    sr[tid + 256] = g_r[b*512 + tid + 256];
    sq[tid]       = qh[b*512 + tid];
    sq[tid + 256] = qh[b*512 + tid + 256];
    __syncthreads();
    int e = ec*8 + warp;
    const float* w1 = rg_w + e*512;
    const float* w2 = qg_w + e*512;
    float s = 0.f;
#pragma unroll
    for (int i = 0; i < 4; i++){
        int k = i*128 + lane*4;
        float4 a = *(const float4*)(w1 + k); float4 x = *(const float4*)(sr + k);
        float4 c = *(const float4*)(w2 + k); float4 y = *(const float4*)(sq + k);
        s += a.x*x.x + a.y*x.y + a.z*x.z + a.w*x.w;
        s += c.x*y.x + c.y*y.y + c.z*y.z + c.w*y.w;
    }
    s = warp_sum(s);
    if (lane == 0) out[b*512 + e] = s + rg_b[e] + qg_b[e];
}

// ---------------- host launch ----------------
extern "C" void kernel_launch(void* const* d_in, const int* in_sizes, int n_in,
                              void* d_out, int out_size)
{
    const float* ctx  = (const float*)d_in[0];
    const float* qout = (const float*)d_in[2];
    const float* qh   = (const float*)d_in[3];
    const float* img  = (const float*)d_in[4];
    const float* fc1w = (const float*)d_in[6];  const float* fc1b = (const float*)d_in[7];
    const float* fc2w = (const float*)d_in[8];  const float* fc2b = (const float*)d_in[9];
    const float* dmw  = (const float*)d_in[10]; const float* dmb  = (const float*)d_in[11];
    const float* msw  = (const float*)d_in[12]; const float* msb  = (const float*)d_in[13];
    const float* rmw  = (const float*)d_in[14]; const float* rmb  = (const float*)d_in[15];
    const float* qmw  = (const float*)d_in[16]; const float* qmb  = (const float*)d_in[17];
    const float* rrw  = (const float*)d_in[18]; const float* rrb  = (const float*)d_in[19];
    const float* rgw  = (const float*)d_in[20]; const float* rgb  = (const float*)d_in[21];
    const float* qgw  = (const float*)d_in[22]; const float* qgb  = (const float*)d_in[23];

    prep_small<<<64, 256>>>(fc1b, fc2b);

    // co (fused perm+concat GEMM, pipelined) + qm GEMM in ONE launch
    gemm_A<<<352, 256>>>(ctx, img, fc1w, fc2w, qout, qmw, qmb);

    // codm(bf16) = co @ dm_w^T + dm_b  (pipelined)
    sgemm_codm<<<dim3(4, 64), 256>>>(dmw, dmb);

    for (int t = 0; t < TT; t++){
        step_proj<<<1024, 256>>>(rmw, rmb, rrw, rrb, t);
        step_fused<<<256, 256>>>(msw, msb);
    }

    final_g<<<2048, 256>>>(rgw, rgb, qgw, qgb, qh, (float*)d_out);
}

// round 9
// speedup vs baseline: 1.8075x; 1.1097x over previous
#include <cuda_runtime.h>
#include <cuda_bf16.h>
#include <cstdint>
#include <math.h>

#define DD 512
#define SS 256
#define BB 32
#define TT 24
#define NROWS (BB*SS)   // 8192

#define CACHE_ROWS 40
// dynamic smem layout (float offsets)
#define OFF_WC   0
#define OFF_R    (CACHE_ROWS*512)          // 20480
#define OFF_ADD  (OFF_R + 512)             // 20992
#define OFF_PO   (OFF_ADD + 512)           // 21504
#define OFF_RN   (OFF_PO + 128)            // 21632
#define OFF_LG   (OFF_RN + 64)             // 21696
#define OFF_RED  (OFF_LG + 32)             // 21728
#define OFF_SW   (OFF_RED + 16)            // 21744
#define OFF_PT   (OFF_SW + 256)            // 22000
#define OFF_MW   (OFF_PT + 256)            // 22256
#define OFF_PB   (OFF_MW + 512)            // 22768
#define SMEM_SCAN_FLOATS (OFF_PB + 128)    // 22896
#define SMEM_SCAN_BYTES  (SMEM_SCAN_FLOATS*4)

// ---------------- device scratch (static: no runtime allocation) ----------------
__device__ float g_bcat[512];                      // fc1_b + fc2_b
__device__ float g_co[NROWS*512];
__device__ __nv_bfloat16 g_codm[NROWS*512];        // bf16: only feeds tanh()
__device__ float g_qm[TT*BB*512];                  // qm projection of all question steps
__device__ float g_r[BB*512];

// ---------------- helpers ----------------
__device__ __forceinline__ float tanh_fast(float x){
    float ax = fabsf(x);
    float e  = __expf(fminf(ax, 15.0f) * 2.0f);
    float t  = __fdividef(e - 1.0f, e + 1.0f);
    return copysignf(t, x);
}

__device__ __forceinline__ float tanh_mufu(float x){
    float y;
    asm("tanh.approx.f32 %0, %1;" : "=f"(y) : "f"(x));
    return y;
}

__device__ __forceinline__ float warp_sum(float v){
#pragma unroll
    for (int o = 16; o; o >>= 1) v += __shfl_xor_sync(0xffffffffu, v, o);
    return v;
}

__device__ __forceinline__ unsigned int s2u(const void* p){
    unsigned int a;
    asm("{ .reg .u64 t; cvta.to.shared.u64 t, %1; cvt.u32.u64 %0, t; }" : "=r"(a) : "l"(p));
    return a;
}

__device__ __forceinline__ float dsmem_ld(unsigned int saddr, unsigned int rank){
    unsigned int ra; float v;
    asm volatile("mapa.shared::cluster.u32 %0, %1, %2;" : "=r"(ra) : "r"(saddr), "r"(rank));
    asm volatile("ld.shared::cluster.f32 %0, [%1];" : "=f"(v) : "r"(ra) : "memory");
    return v;
}

#define CLUSTER_SYNC() do{ \
    asm volatile("barrier.cluster.arrive.aligned;" ::: "memory"); \
    asm volatile("barrier.cluster.wait.aligned;"   ::: "memory"); }while(0)

// ---------------- GEMM building blocks (128x128 tile, BK=16, 256 thr) ----------------
__device__ __forceinline__ void sts16(float* As, float* Bs, int lr0, int lc4,
                                      float4 a0, float4 a1, float4 w0, float4 w1){
    As[(lc4+0)*132 + lr0]      = a0.x; As[(lc4+1)*132 + lr0]      = a0.y;
    As[(lc4+2)*132 + lr0]      = a0.z; As[(lc4+3)*132 + lr0]      = a0.w;
    As[(lc4+0)*132 + lr0 + 64] = a1.x; As[(lc4+1)*132 + lr0 + 64] = a1.y;
    As[(lc4+2)*132 + lr0 + 64] = a1.z; As[(lc4+3)*132 + lr0 + 64] = a1.w;
    Bs[(lc4+0)*132 + lr0]      = w0.x; Bs[(lc4+1)*132 + lr0]      = w0.y;
    Bs[(lc4+2)*132 + lr0]      = w0.z; Bs[(lc4+3)*132 + lr0]      = w0.w;
    Bs[(lc4+0)*132 + lr0 + 64] = w1.x; Bs[(lc4+1)*132 + lr0 + 64] = w1.y;
    Bs[(lc4+2)*132 + lr0 + 64] = w1.z; Bs[(lc4+3)*132 + lr0 + 64] = w1.w;
}

__device__ __forceinline__ void mm16(const float* As, const float* Bs,
                                     float acc[8][8], int tx, int ty){
#pragma unroll
    for (int k = 0; k < 16; k++){
        float4 af0 = *(const float4*)&As[k*132 + ty*8];
        float4 af1 = *(const float4*)&As[k*132 + ty*8 + 4];
        float4 bf0 = *(const float4*)&Bs[k*132 + tx*8];
        float4 bf1 = *(const float4*)&Bs[k*132 + tx*8 + 4];
        float av[8] = {af0.x,af0.y,af0.z,af0.w,af1.x,af1.y,af1.z,af1.w};
        float bv[8] = {bf0.x,bf0.y,bf0.z,bf0.w,bf1.x,bf1.y,bf1.z,bf1.w};
#pragma unroll
        for (int i = 0; i < 8; i++)
#pragma unroll
            for (int j = 0; j < 8; j++)
                acc[i][j] = fmaf(av[i], bv[j], acc[i][j]);
    }
}

// ---------------- tiny prep ----------------
__global__ __launch_bounds__(256) void prep_small(const float* __restrict__ fc1b,
                                                  const float* __restrict__ fc2b){
    int v = blockIdx.x * 256 + threadIdx.x;
    if (v < 512)    g_bcat[v] = fc1b[v] + fc2b[v];
    if (v < BB*512) g_r[v]    = 0.0f;
}

// ---------------- fused GEMM launch A ----------------
__global__ __launch_bounds__(256) void gemm_A(const float* __restrict__ ctx,
                                              const float* __restrict__ img,
                                              const float* __restrict__ fc1w,
                                              const float* __restrict__ fc2w,
                                              const float* __restrict__ qout,
                                              const float* __restrict__ qmw,
                                              const float* __restrict__ qmb)
{
    __shared__ __align__(16) float sh[4*2112];
    const int bid = blockIdx.x;
    const int tid = threadIdx.x;

    if (bid < 256){
        const int m0  = (bid >> 2) * 128;
        const int n0  = (bid & 3) * 128;
        const int tx  = tid & 15, ty = tid >> 4;
        const int lr0 = tid >> 2;
        const int lc4 = (tid & 3) * 4;

        const int r1 = m0 + lr0, r2 = r1 + 64;
        const int p1 = (r1 & 255)*32 + (r1 >> 8);
        const int p2 = (r2 & 255)*32 + (r2 >> 8);

        const float* A1h[2] = { ctx + (size_t)p1*512 + lc4,  img + (size_t)p1*512 + lc4 };
        const float* A2h[2] = { ctx + (size_t)p2*512 + lc4,  img + (size_t)p2*512 + lc4 };
        const float* W1h[2] = { fc1w + (size_t)(n0+lr0)*512 + lc4,
                                fc2w + (size_t)(n0+lr0)*512 + lc4 };
        const float* W2h[2] = { fc1w + (size_t)(n0+lr0+64)*512 + lc4,
                                fc2w + (size_t)(n0+lr0+64)*512 + lc4 };

        float acc[8][8] = {};
        float4 a0, a1, w0, w1;

        a0 = *(const float4*)A1h[0]; a1 = *(const float4*)A2h[0];
        w0 = *(const float4*)W1h[0]; w1 = *(const float4*)W2h[0];
        sts16(sh, sh + 2112, lr0, lc4, a0, a1, w0, w1);
        __syncthreads();

#pragma unroll 1
        for (int it = 0; it < 64; it++){
            const bool has = (it + 1 < 64);
            if (has){
                const int h  = (it+1) >> 5;
                const int kt = ((it+1) & 31) * 16;
                a0 = *(const float4*)((h ? A1h[1] : A1h[0]) + kt);
                a1 = *(const float4*)((h ? A2h[1] : A2h[0]) + kt);
                w0 = *(const float4*)((h ? W1h[1] : W1h[0]) + kt);
                w1 = *(const float4*)((h ? W2h[1] : W2h[0]) + kt);
            }
            const int cur = (it & 1) * 4224;
            mm16(sh + cur, sh + cur + 2112, acc, tx, ty);
            if (has){
                const int nxt = ((it+1) & 1) * 4224;
                sts16(sh + nxt, sh + nxt + 2112, lr0, lc4, a0, a1, w0, w1);
            }
            __syncthreads();
        }

        float4 bb0 = *(const float4*)&g_bcat[n0 + tx*8];
        float4 bb1 = *(const float4*)&g_bcat[n0 + tx*8 + 4];
        float bj[8] = {bb0.x,bb0.y,bb0.z,bb0.w,bb1.x,bb1.y,bb1.z,bb1.w};
#pragma unroll
        for (int i = 0; i < 8; i++){
            int m = m0 + ty*8 + i;
            float4 o0 = make_float4(acc[i][0]+bj[0], acc[i][1]+bj[1],
                                    acc[i][2]+bj[2], acc[i][3]+bj[3]);
            float4 o1 = make_float4(acc[i][4]+bj[4], acc[i][5]+bj[5],
                                    acc[i][6]+bj[6], acc[i][7]+bj[7]);
            *(float4*)&g_co[(size_t)m*512 + n0 + tx*8]     = o0;
            *(float4*)&g_co[(size_t)m*512 + n0 + tx*8 + 4] = o1;
        }
    } else {
        float* As = sh;            // stride 68
        float* Bs = sh + 16*68;
        const int qid = bid - 256;
        const int m0  = (qid >> 3) * 64;
        const int n0  = (qid & 7) * 64;
        const int tx  = tid & 15, ty = tid >> 4;
        const int lr0 = tid >> 2;
        const int lc4 = (tid & 3) * 4;

        float acc[4][4] = {};
        const float* A1 = qout + (size_t)(m0 + lr0)*512 + lc4;
        const float* W1 = qmw  + (size_t)(n0 + lr0)*512 + lc4;

        for (int kt = 0; kt < 512; kt += 16){
            float4 a0 = *(const float4*)(A1 + kt);
            float4 w0 = *(const float4*)(W1 + kt);
            __syncthreads();
            As[(lc4+0)*68 + lr0] = a0.x; As[(lc4+1)*68 + lr0] = a0.y;
            As[(lc4+2)*68 + lr0] = a0.z; As[(lc4+3)*68 + lr0] = a0.w;
            Bs[(lc4+0)*68 + lr0] = w0.x; Bs[(lc4+1)*68 + lr0] = w0.y;
            Bs[(lc4+2)*68 + lr0] = w0.z; Bs[(lc4+3)*68 + lr0] = w0.w;
            __syncthreads();
#pragma unroll
            for (int k = 0; k < 16; k++){
                float4 av = *(const float4*)&As[k*68 + ty*4];
                float4 bv = *(const float4*)&Bs[k*68 + tx*4];
                float aa[4] = {av.x,av.y,av.z,av.w};
                float bb[4] = {bv.x,bv.y,bv.z,bv.w};
#pragma unroll
                for (int i = 0; i < 4; i++)
#pragma unroll
                    for (int j = 0; j < 4; j++)
                        acc[i][j] = fmaf(aa[i], bb[j], acc[i][j]);
            }
        }

        float4 bq = *(const float4*)&qmb[n0 + tx*4];
        float bj[4] = {bq.x,bq.y,bq.z,bq.w};
#pragma unroll
        for (int i = 0; i < 4; i++){
            int m = m0 + ty*4 + i;
            float4 o = make_float4(acc[i][0]+bj[0], acc[i][1]+bj[1],
                                   acc[i][2]+bj[2], acc[i][3]+bj[3]);
            *(float4*)&g_qm[(size_t)m*512 + n0 + tx*4] = o;
        }
    }
}

// ---------------- codm GEMM (double-buffered): codm(bf16) = co @ dm_w^T + dm_b ----------------
__global__ __launch_bounds__(256) void sgemm_codm(const float* __restrict__ W,
                                                  const float* __restrict__ bias)
{
    __shared__ __align__(16) float sh[4*2112];
    const int m0  = blockIdx.y * 128;
    const int n0  = blockIdx.x * 128;
    const int tid = threadIdx.x;
    const int tx  = tid & 15, ty = tid >> 4;
    const int lr0 = tid >> 2;
    const int lc4 = (tid & 3) * 4;

    const float* A1 = g_co + (size_t)(m0 + lr0) * 512 + lc4;
    const float* A2 = A1 + (size_t)64*512;
    const float* W1 = W + (size_t)(n0 + lr0) * 512 + lc4;
    const float* W2 = W1 + (size_t)64*512;

    float acc[8][8] = {};
    float4 a0 = *(const float4*)A1;
    float4 a1 = *(const float4*)A2;
    float4 w0 = *(const float4*)W1;
    float4 w1 = *(const float4*)W2;
    sts16(sh, sh + 2112, lr0, lc4, a0, a1, w0, w1);
    __syncthreads();

#pragma unroll 1
    for (int it = 0; it < 32; it++){
        const bool has = (it + 1 < 32);
        if (has){
            const int kt = (it+1) * 16;
            a0 = *(const float4*)(A1 + kt); a1 = *(const float4*)(A2 + kt);
            w0 = *(const float4*)(W1 + kt); w1 = *(const float4*)(W2 + kt);
        }
        const int cur = (it & 1) * 4224;
        mm16(sh + cur, sh + cur + 2112, acc, tx, ty);
        if (has){
            const int nxt = ((it+1) & 1) * 4224;
            sts16(sh + nxt, sh + nxt + 2112, lr0, lc4, a0, a1, w0, w1);
        }
        __syncthreads();
    }

    float4 bb0 = *(const float4*)&bias[n0 + tx*8];
    float4 bb1 = *(const float4*)&bias[n0 + tx*8 + 4];
    float bj[8] = {bb0.x,bb0.y,bb0.z,bb0.w,bb1.x,bb1.y,bb1.z,bb1.w};
#pragma unroll
    for (int i = 0; i < 8; i++){
        int m = m0 + ty*8 + i;
        __nv_bfloat162 p[4];
        p[0] = __floats2bfloat162_rn(acc[i][0]+bj[0], acc[i][1]+bj[1]);
        p[1] = __floats2bfloat162_rn(acc[i][2]+bj[2], acc[i][3]+bj[3]);
        p[2] = __floats2bfloat162_rn(acc[i][4]+bj[4], acc[i][5]+bj[5]);
        p[3] = __floats2bfloat162_rn(acc[i][6]+bj[6], acc[i][7]+bj[7]);
        *(uint4*)&g_codm[(size_t)m*512 + n0 + tx*8] = *(uint4*)p;
    }
}

// ---------------- persistent cluster scan: the ENTIRE 24-step recurrence ----------------
// grid 256 = 32 batches x 8-CTA clusters, ONE launch for all T steps.
// Per CTA: owns 128 proj rows (ranks 0-3: rm->add, ranks 4-7: rr->trr), 40 cached in smem.
// 3 cluster syncs per step; all intermediates exchanged via DSMEM.
// CRITICAL: trailing CLUSTER_SYNC before exit — no CTA may die while a peer can
// still issue ld.shared::cluster into its SMEM.
__global__ void __launch_bounds__(256, 1) __cluster_dims__(8, 1, 1)
scan_cluster(const float* __restrict__ rm_w, const float* __restrict__ rm_b,
             const float* __restrict__ rr_w, const float* __restrict__ rr_b,
             const float* __restrict__ ms_w, const float* __restrict__ ms_b)
{
    extern __shared__ float sm[];
    float* wc    = sm + OFF_WC;
    float* s_r   = sm + OFF_R;
    float* s_add = sm + OFF_ADD;
    float* s_po  = sm + OFF_PO;
    float* s_rn  = sm + OFF_RN;
    float* s_lg  = sm + OFF_LG;
    float* s_red = sm + OFF_RED;
    float* s_sw  = sm + OFF_SW;
    float* s_pt  = sm + OFF_PT;
    float* s_mw  = sm + OFF_MW;
    float* s_pb  = sm + OFF_PB;

    const int tid = threadIdx.x, lane = tid & 31, warp = tid >> 5;
    unsigned int rank; asm("mov.u32 %0, %%cluster_ctarank;" : "=r"(rank));
    const int b = blockIdx.x >> 3;
    const bool is_rm = (rank < 4);

    const float* wsrc = is_rm ? (rm_w + (size_t)rank*128*512)
                              : (rr_w + (size_t)(rank-4)*128*512);
    const float* bsrc = is_rm ? (rm_b + rank*128) : (rr_b + (rank-4)*128);

    // ---- init: weight cache, biases, ms_w, r = 0 ----
    for (int i = tid; i < CACHE_ROWS*128; i += 256)
        ((float4*)wc)[i] = ((const float4*)wsrc)[i];
    if (tid < 128) s_pb[tid] = bsrc[tid];
    s_mw[tid]       = ms_w[tid];
    s_mw[tid + 256] = ms_w[tid + 256];
    s_r[tid] = 0.f; s_r[tid + 256] = 0.f;
    const float msb0 = ms_b[0];
    __syncthreads();

    for (int t = 0; t < TT; t++){
        // ================= P: proj — 16 rows per warp, quads of 4 interleaved
        float4 r0 = *(const float4*)&s_r[lane*4];
        float4 r1 = *(const float4*)&s_r[lane*4 + 128];
        float4 r2 = *(const float4*)&s_r[lane*4 + 256];
        float4 r3 = *(const float4*)&s_r[lane*4 + 384];
#pragma unroll
        for (int g = 0; g < 4; g++){
            const int q0 = warp*16 + g*4;
            float sums[4];
            if (q0 + 3 < CACHE_ROWS){
#pragma unroll
                for (int q = 0; q < 4; q++){
                    const float* w = wc + (q0 + q)*512;
                    float4 w0 = *(const float4*)(w + lane*4);
                    float4 w1 = *(const float4*)(w + lane*4 + 128);
                    float4 w2 = *(const float4*)(w + lane*4 + 256);
                    float4 w3 = *(const float4*)(w + lane*4 + 384);
                    sums[q] = w0.x*r0.x + w0.y*r0.y + w0.z*r0.z + w0.w*r0.w
                            + w1.x*r1.x + w1.y*r1.y + w1.z*r1.z + w1.w*r1.w
                            + w2.x*r2.x + w2.y*r2.y + w2.z*r2.z + w2.w*r2.w
                            + w3.x*r3.x + w3.y*r3.y + w3.z*r3.z + w3.w*r3.w;
                }
            } else {
#pragma unroll
                for (int q = 0; q < 4; q++){
                    const float* w = wsrc + (size_t)(q0 + q)*512;
                    float4 w0 = *(const float4*)(w + lane*4);
                    float4 w1 = *(const float4*)(w + lane*4 + 128);
                    float4 w2 = *(const float4*)(w + lane*4 + 256);
                    float4 w3 = *(const float4*)(w + lane*4 + 384);
                    sums[q] = w0.x*r0.x + w0.y*r0.y + w0.z*r0.z + w0.w*r0.w
                            + w1.x*r1.x + w1.y*r1.y + w1.z*r1.z + w1.w*r1.w
                            + w2.x*r2.x + w2.y*r2.y + w2.z*r2.z + w2.w*r2.w
                            + w3.x*r3.x + w3.y*r3.y + w3.z*r3.z + w3.w*r3.w;
                }
            }
#pragma unroll
            for (int q = 0; q < 4; q++) sums[q] = warp_sum(sums[q]);
            if (lane < 4){
                float v = (lane == 0) ? sums[0] : (lane == 1) ? sums[1]
                        : (lane == 2) ? sums[2] : sums[3];
                int lr = q0 + lane;
                v += s_pb[lr];
                if (is_rm) v += g_qm[(size_t)(t*BB + b)*512 + rank*128 + lr];
                else       v  = tanh_fast(v);
                s_po[lr] = v;
            }
        }
        CLUSTER_SYNC();                         // s_po visible cluster-wide

        // gather full add[512] from ranks 0-3 via DSMEM
        {
            unsigned int sa = s2u(&s_po[tid & 127]);
            s_add[tid]       = dsmem_ld(sa, (unsigned int)(tid >> 7));
            s_add[tid + 256] = dsmem_ld(sa, (unsigned int)((tid + 256) >> 7));
        }
        __syncthreads();

        // ================= L: 32 logits rows (rank slice), 4 per warp
        {
            float acc4[4] = {0.f, 0.f, 0.f, 0.f};
            const __nv_bfloat16* cd0 = g_codm + (size_t)(b*256 + (int)rank*32 + warp*4)*512;
#pragma unroll
            for (int rw = 0; rw < 4; rw++){
                const __nv_bfloat16* cd = cd0 + (size_t)rw*512;
                float s = 0.f;
#pragma unroll
                for (int i = 0; i < 4; i++){
                    int k = i*128 + lane*4;
                    uint2 u = *(const uint2*)(cd + k);
                    float2 c01 = __bfloat1622float2(*(const __nv_bfloat162*)&u.x);
                    float2 c23 = __bfloat1622float2(*(const __nv_bfloat162*)&u.y);
                    float4 a = *(const float4*)(s_add + k);
                    float4 m = *(const float4*)(s_mw + k);
                    s += tanh_mufu(c01.x + a.x) * m.x;
                    s += tanh_mufu(c01.y + a.y) * m.y;
                    s += tanh_mufu(c23.x + a.z) * m.z;
                    s += tanh_mufu(c23.y + a.w) * m.w;
                }
                acc4[rw] = s;
            }
#pragma unroll
            for (int rw = 0; rw < 4; rw++) acc4[rw] = warp_sum(acc4[rw]);
            if (lane < 4){
                float v = (lane == 0) ? acc4[0] : (lane == 1) ? acc4[1]
                        : (lane == 2) ? acc4[2] : acc4[3];
                s_lg[warp*4 + lane] = v + msb0;
            }
        }
        CLUSTER_SYNC();                         // s_lg visible cluster-wide

        // gather 256 logits + redundant softmax
        {
            float l = dsmem_ld(s2u(&s_lg[tid & 31]), (unsigned int)(tid >> 5));
            float m = l;
#pragma unroll
            for (int o = 16; o; o >>= 1) m = fmaxf(m, __shfl_xor_sync(0xffffffffu, m, o));
            if (lane == 0) s_red[warp] = m;
            __syncthreads();
            float mx = s_red[0];
#pragma unroll
            for (int i = 1; i < 8; i++) mx = fmaxf(mx, s_red[i]);
            float ex = __expf(l - mx);
            float smm = warp_sum(ex);
            if (lane == 0) s_red[8 + warp] = smm;
            __syncthreads();
            float tot = s_red[8];
#pragma unroll
            for (int i = 9; i < 16; i++) tot += s_red[i];
            s_sw[tid] = ex * (1.0f / tot);
        }
        __syncthreads();

        // ================= U: e-slice [rank*64, +64), weighted sum of co
        {
            int e  = (int)rank*64 + (tid & 63);
            int sq = tid >> 6;
            const float* cb = g_co + (size_t)(b*256 + sq*64)*512 + e;
            const float* wv = s_sw + sq*64;
            float acc = 0.f;
#pragma unroll 8
            for (int s = 0; s < 64; s++)
                acc = fmaf(wv[s], cb[(size_t)s*512], acc);
            s_pt[tid] = acc;
            __syncthreads();
            if (tid < 64){
                int eo = (int)rank*64 + tid;
                float trr = dsmem_ld(s2u(&s_po[eo & 127]), 4u + (unsigned int)(eo >> 7));
                float v = s_pt[tid] + s_pt[tid+64] + s_pt[tid+128] + s_pt[tid+192] + trr;
                s_rn[tid] = v;
                if (t == TT-1) g_r[b*512 + eo] = v;
            }
        }
        CLUSTER_SYNC();                         // s_rn visible cluster-wide

        // gather full r[512] for next step (skip on last step — result already in g_r)
        if (t < TT-1){
            unsigned int sa = s2u(&s_rn[tid & 63]);
            s_r[tid]       = dsmem_ld(sa, (unsigned int)(tid >> 6));
            s_r[tid + 256] = dsmem_ld(sa, (unsigned int)((tid + 256) >> 6));
            __syncthreads();
        }
    }

    // no CTA may exit while a peer might still read its SMEM
    CLUSTER_SYNC();
}

// ---------------- final: g = rg(r) + qg(qh) ----------------
__global__ __launch_bounds__(256) void final_g(const float* __restrict__ rg_w,
                                               const float* __restrict__ rg_b,
                                               const float* __restrict__ qg_w,
                                               const float* __restrict__ qg_b,
                                               const float* __restrict__ qh,
                                               float* __restrict__ out)
{
    __shared__ __align__(16) float sr[512];
    __shared__ __align__(16) float sq[512];
    int bx  = blockIdx.x;
    int b   = bx >> 6, ec = bx & 63;
    int tid = threadIdx.x, lane = tid & 31, warp = tid >> 5;
    sr[tid]       = g_r[b*512 + tid];
    sr[tid + 256] = g_r[b*512 + tid + 256];
    sq[tid]       = qh[b*512 + tid];
    sq[tid + 256] = qh[b*512 + tid + 256];
    __syncthreads();
    int e = ec*8 + warp;
    const float* w1 = rg_w + e*512;
    const float* w2 = qg_w + e*512;
    float s = 0.f;
#pragma unroll
    for (int i = 0; i < 4; i++){
        int k = i*128 + lane*4;
        float4 a = *(const float4*)(w1 + k); float4 x = *(const float4*)(sr + k);
        float4 c = *(const float4*)(w2 + k); float4 y = *(const float4*)(sq + k);
        s += a.x*x.x + a.y*x.y + a.z*x.z + a.w*x.w;
        s += c.x*y.x + c.y*y.y + c.z*y.z + c.w*y.w;
    }
    s = warp_sum(s);
    if (lane == 0) out[b*512 + e] = s + rg_b[e] + qg_b[e];
}

// ---------------- host launch ----------------
extern "C" void kernel_launch(void* const* d_in, const int* in_sizes, int n_in,
                              void* d_out, int out_size)
{
    const float* ctx  = (const float*)d_in[0];
    const float* qout = (const float*)d_in[2];
    const float* qh   = (const float*)d_in[3];
    const float* img  = (const float*)d_in[4];
    const float* fc1w = (const float*)d_in[6];  const float* fc1b = (const float*)d_in[7];
    const float* fc2w = (const float*)d_in[8];  const float* fc2b = (const float*)d_in[9];
    const float* dmw  = (const float*)d_in[10]; const float* dmb  = (const float*)d_in[11];
    const float* msw  = (const float*)d_in[12]; const float* msb  = (const float*)d_in[13];
    const float* rmw  = (const float*)d_in[14]; const float* rmb  = (const float*)d_in[15];
    const float* qmw  = (const float*)d_in[16]; const float* qmb  = (const float*)d_in[17];
    const float* rrw  = (const float*)d_in[18]; const float* rrb  = (const float*)d_in[19];
    const float* rgw  = (const float*)d_in[20]; const float* rgb  = (const float*)d_in[21];
    const float* qgw  = (const float*)d_in[22]; const float* qgb  = (const float*)d_in[23];

    cudaFuncSetAttribute(scan_cluster, cudaFuncAttributeMaxDynamicSharedMemorySize,
                         SMEM_SCAN_BYTES);

    prep_small<<<64, 256>>>(fc1b, fc2b);

    // co (fused perm+concat GEMM, pipelined) + qm GEMM in ONE launch
    gemm_A<<<352, 256>>>(ctx, img, fc1w, fc2w, qout, qmw, qmb);

    // codm(bf16) = co @ dm_w^T + dm_b  (pipelined)
    sgemm_codm<<<dim3(4, 64), 256>>>(dmw, dmb);

    // ENTIRE scan: one launch, 32 independent 8-CTA clusters (one per batch)
    scan_cluster<<<256, 256, SMEM_SCAN_BYTES>>>(rmw, rmb, rrw, rrb, msw, msb);

    final_g<<<2048, 256>>>(rgw, rgb, qgw, qgb, qh, (float*)d_out);
}